// round 4
// baseline (speedup 1.0000x reference)
#include <cuda_runtime.h>
#include <cuda_bf16.h>

// BlockAttnRes: per-token block attention over N=9 source rows of D=512.
//   score_n = dot(src_n, w) / sqrt(mean(src_n^2)+1e-6),  alpha = softmax(score),
//   h = sum_n alpha_n * src_n.
//
// R4: persistent grid (152 SMs x 4 CTAs) with register double-buffering.
// Each iteration issues next token's 9 LDG.128 BEFORE computing on the
// current token, so every warp keeps ~4.6 KB in flight through the whole
// compute/store phase -> continuous DRAM request stream (R3 showed DRAM
// idle ~20% from bursty per-CTA load/compute serialization).

#define NN 9
#define DD 512
#define THREADS 128
#define GRID 608   // 152 SMs * 4 CTAs/SM

__global__ __launch_bounds__(THREADS, 4)
void blockattn_kernel(const float* __restrict__ src,
                      const float* __restrict__ queries,
                      const int*   __restrict__ layer_idx,
                      float*       __restrict__ out,
                      int tokens)
{
    // [parity][0=ss,1=dt][row][warp]
    __shared__ float s_red[2][2][NN][4];

    const int tid  = threadIdx.x;
    const int lane = tid & 31;
    const int warp = tid >> 5;
    const int G    = gridDim.x;

    const int li = __ldg(layer_idx);
    const float4 w4 = __ldg(reinterpret_cast<const float4*>(queries + (long long)li * DD) + tid);

    const float4* srcv = reinterpret_cast<const float4*>(src);
    float4*       outv = reinterpret_cast<float4*>(out);

    long long t = blockIdx.x;
    float4 vc[NN], vn[NN];

    if (t < tokens) {
        const float4* b = srcv + t * (NN * DD / 4);
#pragma unroll
        for (int n = 0; n < NN; n++)
            vc[n] = __ldcs(b + n * (DD / 4) + tid);
    }

    int p = 0;
    for (; t < tokens; t += G, p ^= 1) {
        // ---- Prefetch next token's rows (in flight during compute below) ----
        const long long tn = t + G;
        if (tn < tokens) {
            const float4* b = srcv + tn * (NN * DD / 4);
#pragma unroll
            for (int n = 0; n < NN; n++)
                vn[n] = __ldcs(b + n * (DD / 4) + tid);
        }

        // ---- Per-row partials: sumsq & dot, warp-reduce, stash ----
#pragma unroll
        for (int n = 0; n < NN; n++) {
            const float4 a = vc[n];
            float ssn = a.x * a.x + a.y * a.y + a.z * a.z + a.w * a.w;
            float dtn = a.x * w4.x + a.y * w4.y + a.z * w4.z + a.w * w4.w;
#pragma unroll
            for (int o = 16; o > 0; o >>= 1) {
                ssn += __shfl_xor_sync(0xffffffffu, ssn, o);
                dtn += __shfl_xor_sync(0xffffffffu, dtn, o);
            }
            if (lane == 0) {
                s_red[p][0][n][warp] = ssn;
                s_red[p][1][n][warp] = dtn;
            }
        }
        __syncthreads();   // single barrier per iteration (parity buffers)

        // ---- Softmax over 9, redundantly per thread (broadcast LDS) ----
        float alpha[NN];
        {
            float mx = -3.4e38f;
#pragma unroll
            for (int n = 0; n < NN; n++) {
                const float S  = s_red[p][0][n][0] + s_red[p][0][n][1]
                               + s_red[p][0][n][2] + s_red[p][0][n][3];
                const float Dt = s_red[p][1][n][0] + s_red[p][1][n][1]
                               + s_red[p][1][n][2] + s_red[p][1][n][3];
                alpha[n] = Dt * rsqrtf(S * (1.0f / DD) + 1e-6f);
                mx = fmaxf(mx, alpha[n]);
            }
            float sum = 0.0f;
#pragma unroll
            for (int n = 0; n < NN; n++) {
                alpha[n] = __expf(alpha[n] - mx);
                sum += alpha[n];
            }
            const float inv = 1.0f / sum;
#pragma unroll
            for (int n = 0; n < NN; n++)
                alpha[n] *= inv;
        }

        // ---- Weighted sum from registers; streaming store ----
        float4 o = make_float4(0.f, 0.f, 0.f, 0.f);
#pragma unroll
        for (int n = 0; n < NN; n++) {
            o.x += alpha[n] * vc[n].x;
            o.y += alpha[n] * vc[n].y;
            o.z += alpha[n] * vc[n].z;
            o.w += alpha[n] * vc[n].w;
        }
        __stcs(outv + t * (DD / 4) + tid, o);

        // ---- Rotate buffers ----
#pragma unroll
        for (int n = 0; n < NN; n++)
            vc[n] = vn[n];
    }
}

extern "C" void kernel_launch(void* const* d_in, const int* in_sizes, int n_in,
                              void* d_out, int out_size)
{
    const float* src     = (const float*)d_in[0];
    const float* queries = (const float*)d_in[1];
    const int*   lidx    = (const int*)d_in[2];
    float*       out     = (float*)d_out;

    const int tokens = in_sizes[0] / (NN * DD);   // B*T = 32768
    const int grid = (tokens < GRID) ? tokens : GRID;
    blockattn_kernel<<<grid, THREADS>>>(src, queries, lidx, out, tokens);
}

// round 5
// speedup vs baseline: 1.0253x; 1.0253x over previous
#include <cuda_runtime.h>
#include <cuda_bf16.h>
#include <cstdint>

// BlockAttnRes: per-token block attention over N=9 source rows of D=512.
//   score_n = dot(src_n, w) / sqrt(mean(src_n^2)+1e-6),  alpha = softmax(score),
//   h = sum_n alpha_n * src_n.
//
// R5: persistent grid, register-resident compute (R3 skeleton, 64 regs,
// 8 CTAs/SM) + cp.async (LDGSTS) prefetch of the NEXT token into a
// thread-private SMEM staging buffer. LDGSTS holds the in-flight data in
// smem, not registers (R4's register prefetch cost occupancy). Each thread
// reads back only the bytes its own cp.async wrote -> per-thread
// wait_group, no extra barrier. DRAM stream stays continuous through the
// compute phase.

#define NN 9
#define DD 512
#define THREADS 128
#define CTAS_PER_SM 8
#define GRID (152 * CTAS_PER_SM)

__device__ __forceinline__ uint32_t smem_u32(const void* p) {
    return (uint32_t)__cvta_generic_to_shared(p);
}

__global__ __launch_bounds__(THREADS, CTAS_PER_SM)
void blockattn_kernel(const float* __restrict__ src,
                      const float* __restrict__ queries,
                      const int*   __restrict__ layer_idx,
                      float*       __restrict__ out,
                      int tokens)
{
    __shared__ __align__(16) float buf[NN * DD];        // 18432 B staging
    __shared__ float s_red[2][2][NN][4];                // [parity][ss/dt][row][warp]

    const int tid  = threadIdx.x;
    const int lane = tid & 31;
    const int warp = tid >> 5;
    const int G    = gridDim.x;

    const int li = __ldg(layer_idx);
    const float4 w4 = __ldg(reinterpret_cast<const float4*>(queries + (long long)li * DD) + tid);

    const float4* bufv = reinterpret_cast<const float4*>(buf);

    // Per-thread staging addresses (each thread owns the same 9 float4 slots
    // it fills with cp.async — no cross-thread smem sharing in buf).
    uint32_t s_dst[NN];
#pragma unroll
    for (int n = 0; n < NN; n++)
        s_dst[n] = smem_u32(&buf[n * DD + tid * 4]);

    long long t = blockIdx.x;

    // ---- Prologue: prefetch first token ----
    if (t < tokens) {
        const float* g = src + t * (long long)(NN * DD) + tid * 4;
#pragma unroll
        for (int n = 0; n < NN; n++)
            asm volatile("cp.async.cg.shared.global [%0], [%1], 16;"
                         :: "r"(s_dst[n]), "l"(g + n * DD) : "memory");
        asm volatile("cp.async.commit_group;" ::: "memory");
    }

    int p = 0;
    for (; t < tokens; t += G, p ^= 1) {
        // ---- Drain this thread's prefetch; copy staging -> registers ----
        asm volatile("cp.async.wait_group 0;" ::: "memory");
        float4 vc[NN];
#pragma unroll
        for (int n = 0; n < NN; n++)
            vc[n] = bufv[n * (DD / 4) + tid];

        // ---- Immediately issue next token's prefetch (in flight during
        //      all compute below). Safe: LDS above already executed; the
        //      cp.async write lands long after. ----
        const long long tn = t + G;
        if (tn < tokens) {
            const float* g = src + tn * (long long)(NN * DD) + tid * 4;
#pragma unroll
            for (int n = 0; n < NN; n++)
                asm volatile("cp.async.cg.shared.global [%0], [%1], 16;"
                             :: "r"(s_dst[n]), "l"(g + n * DD) : "memory");
            asm volatile("cp.async.commit_group;" ::: "memory");
        }

        // ---- Per-row partials: sumsq & dot, warp-reduce, stash ----
#pragma unroll
        for (int n = 0; n < NN; n++) {
            const float4 a = vc[n];
            float ssn = a.x * a.x + a.y * a.y + a.z * a.z + a.w * a.w;
            float dtn = a.x * w4.x + a.y * w4.y + a.z * w4.z + a.w * w4.w;
#pragma unroll
            for (int o = 16; o > 0; o >>= 1) {
                ssn += __shfl_xor_sync(0xffffffffu, ssn, o);
                dtn += __shfl_xor_sync(0xffffffffu, dtn, o);
            }
            if (lane == 0) {
                s_red[p][0][n][warp] = ssn;
                s_red[p][1][n][warp] = dtn;
            }
        }
        __syncthreads();   // single barrier per iteration (parity buffers)

        // ---- Softmax over 9, redundantly per thread (broadcast LDS) ----
        float alpha[NN];
        {
            float mx = -3.4e38f;
#pragma unroll
            for (int n = 0; n < NN; n++) {
                const float S  = s_red[p][0][n][0] + s_red[p][0][n][1]
                               + s_red[p][0][n][2] + s_red[p][0][n][3];
                const float Dt = s_red[p][1][n][0] + s_red[p][1][n][1]
                               + s_red[p][1][n][2] + s_red[p][1][n][3];
                alpha[n] = Dt * rsqrtf(S * (1.0f / DD) + 1e-6f);
                mx = fmaxf(mx, alpha[n]);
            }
            float sum = 0.0f;
#pragma unroll
            for (int n = 0; n < NN; n++) {
                alpha[n] = __expf(alpha[n] - mx);
                sum += alpha[n];
            }
            const float inv = 1.0f / sum;
#pragma unroll
            for (int n = 0; n < NN; n++)
                alpha[n] *= inv;
        }

        // ---- Weighted sum from registers; streaming store ----
        float4 o = make_float4(0.f, 0.f, 0.f, 0.f);
#pragma unroll
        for (int n = 0; n < NN; n++) {
            o.x += alpha[n] * vc[n].x;
            o.y += alpha[n] * vc[n].y;
            o.z += alpha[n] * vc[n].z;
            o.w += alpha[n] * vc[n].w;
        }
        __stcs(reinterpret_cast<float4*>(out) + t * (DD / 4) + tid, o);
    }
}

extern "C" void kernel_launch(void* const* d_in, const int* in_sizes, int n_in,
                              void* d_out, int out_size)
{
    const float* src     = (const float*)d_in[0];
    const float* queries = (const float*)d_in[1];
    const int*   lidx    = (const int*)d_in[2];
    float*       out     = (float*)d_out;

    const int tokens = in_sizes[0] / (NN * DD);   // B*T = 32768
    const int grid = (tokens < GRID) ? tokens : GRID;
    blockattn_kernel<<<grid, THREADS>>>(src, queries, lidx, out, tokens);
}